// round 2
// baseline (speedup 1.0000x reference)
#include <cuda_runtime.h>
#include <math.h>

// Problem constants (fixed by the dataset)
#define BB 2
#define HH 16
#define NN 8192
#define HD 128
#define NOFF 20

#define FULLMASK 0xffffffffu

// queries per warp
#define QT 8
// warps per block
#define NWARP 8

// delta -> offset index (compile-time foldable under full unroll)
__device__ __host__ __forceinline__ constexpr int j_of(int d) {
    switch (d) {
        case 1: return 0;  case 2: return 1;  case 3: return 2;  case 4: return 3;
        case 5: return 4;  case 6: return 5;  case 7: return 6;  case 8: return 7;
        case 9: return 8;  case 11: return 9; case 13: return 10; case 15: return 11;
        case 16: return 12; case 23: return 13; case 32: return 14; case 64: return 15;
        case 128: return 16; case 256: return 17; case 512: return 18; case 1024: return 19;
        default: return -1;
    }
}

__device__ __forceinline__ float warp_sum(float x) {
    x += __shfl_xor_sync(FULLMASK, x, 16);
    x += __shfl_xor_sync(FULLMASK, x, 8);
    x += __shfl_xor_sync(FULLMASK, x, 4);
    x += __shfl_xor_sync(FULLMASK, x, 2);
    x += __shfl_xor_sync(FULLMASK, x, 1);
    return x;
}

__device__ __forceinline__ float warp_max(float x) {
    x = fmaxf(x, __shfl_xor_sync(FULLMASK, x, 16));
    x = fmaxf(x, __shfl_xor_sync(FULLMASK, x, 8));
    x = fmaxf(x, __shfl_xor_sync(FULLMASK, x, 4));
    x = fmaxf(x, __shfl_xor_sync(FULLMASK, x, 2));
    x = fmaxf(x, __shfl_xor_sync(FULLMASK, x, 1));
    return x;
}

// Number of unique rows (as offsets m = n0 - row) touched by 8 consecutive queries
#define NM 78

__global__ void __launch_bounds__(256)
dsqg_kernel(const float* __restrict__ q,
            const float* __restrict__ k,
            const float* __restrict__ v,
            const float* __restrict__ pb,   // [J, H]
            const float* __restrict__ se,   // [J, HD]
            float* __restrict__ out)
{
    // unique-m table: union over deltas of {delta - t, t in [0,8)} intersected with useful rows
    const int MTAB[NM] = {
        -6,-5,-4,-3,-2,-1,0,1,2,3,4,5,6,7,8,9,10,11,12,13,14,15,16,
        17,18,19,20,21,22,23,
        25,26,27,28,29,30,31,32,
        57,58,59,60,61,62,63,64,
        121,122,123,124,125,126,127,128,
        249,250,251,252,253,254,255,256,
        505,506,507,508,509,510,511,512,
        1017,1018,1019,1020,1021,1022,1023,1024
    };

    const int lane = threadIdx.x & 31;
    const int warp = threadIdx.x >> 5;
    // bh fastest in blockIdx -> concurrent wave covers a narrow n-window over all (b,h):
    // keeps the delta<=1024 reuse window resident in L2.
    const int bh   = blockIdx.x & (BB * HH - 1);
    const int tile = blockIdx.x >> 5;
    const int h    = bh & (HH - 1);
    const int n0   = tile * (NWARP * QT) + warp * QT;

    const size_t base = (size_t)bh * ((size_t)NN * HD);
    const float* qr = q + base + (size_t)n0 * HD + lane * 4;
    const float* kr = k + base + lane * 4;
    const float* vr = v + base + lane * 4;
    float* orow = out + base + (size_t)n0 * HD + lane * 4;

    const float sc = 0.08838834764831845f;  // 1/sqrt(128)
    const float NEG_INF = __int_as_float(0xff800000);

    // ---- load q tile: 8 queries x 4 floats per lane ----
    float4 q4[QT];
#pragma unroll
    for (int t = 0; t < QT; ++t)
        q4[t] = *(const float4*)(qr + t * HD);

    // ---- bias: Bv[t] holds (pos_bias[j,h] + sc * (q_t . se_j)) in lane j (<20) ----
    float pbl = (lane < NOFF) ? pb[lane * HH + h] : 0.f;
    float Bv[QT];
#pragma unroll
    for (int t = 0; t < QT; ++t) Bv[t] = 0.f;
#pragma unroll
    for (int j = 0; j < NOFF; ++j) {
        const float4 s4 = *(const float4*)(se + j * HD + lane * 4);
#pragma unroll
        for (int t = 0; t < QT; ++t) {
            float p = q4[t].x * s4.x + q4[t].y * s4.y + q4[t].z * s4.z + q4[t].w * s4.w;
            p = warp_sum(p);
            if (lane == j) Bv[t] = pbl + sc * p;
        }
    }

    // ---- scores: each unique k row loaded once, applied to all (t, j=j_of(m+t)) ----
    float S[QT];
#pragma unroll
    for (int t = 0; t < QT; ++t) S[t] = NEG_INF;

#pragma unroll
    for (int mi = 0; mi < NM; ++mi) {
        const int m = MTAB[mi];
        if (n0 >= m) {  // warp-uniform: row n0-m valid
            const float4 k4 = *(const float4*)(kr + (size_t)(n0 - m) * HD);
#pragma unroll
            for (int t = 0; t < QT; ++t) {
                const int j = j_of(m + t);
                if (j >= 0) {
                    float p = q4[t].x * k4.x + q4[t].y * k4.y + q4[t].z * k4.z + q4[t].w * k4.w;
                    p = warp_sum(p);
                    if (lane == j) S[t] = sc * p + Bv[t];
                }
            }
        }
    }

    // ---- softmax over the 20 offsets (lane-parallel, lanes >= 20 hold -inf) ----
    float P[QT];
#pragma unroll
    for (int t = 0; t < QT; ++t) {
        const float s  = S[t];
        const float mx = warp_max(s);
        const float ms = (mx == NEG_INF) ? 0.f : mx;
        const float e  = __expf(s - ms);          // exp(-inf) -> 0 for invalid/padding lanes
        const float sum = warp_sum(e);
        const float inv = (sum > 0.f) ? (1.0f / sum) : 0.f;
        P[t] = e * inv;
    }

    // ---- output: each unique v row loaded once, weighted into all dependent queries ----
    float4 o4[QT];
#pragma unroll
    for (int t = 0; t < QT; ++t) { o4[t].x = 0.f; o4[t].y = 0.f; o4[t].z = 0.f; o4[t].w = 0.f; }

#pragma unroll
    for (int mi = 0; mi < NM; ++mi) {
        const int m = MTAB[mi];
        if (n0 >= m) {
            const float4 v4 = *(const float4*)(vr + (size_t)(n0 - m) * HD);
#pragma unroll
            for (int t = 0; t < QT; ++t) {
                const int j = j_of(m + t);
                if (j >= 0) {
                    const float pj = __shfl_sync(FULLMASK, P[t], j);
                    o4[t].x += pj * v4.x;
                    o4[t].y += pj * v4.y;
                    o4[t].z += pj * v4.z;
                    o4[t].w += pj * v4.w;
                }
            }
        }
    }

#pragma unroll
    for (int t = 0; t < QT; ++t)
        *(float4*)(orow + t * HD) = o4[t];
}

extern "C" void kernel_launch(void* const* d_in, const int* in_sizes, int n_in,
                              void* d_out, int out_size) {
    const float* q  = (const float*)d_in[0];
    const float* k  = (const float*)d_in[1];
    const float* v  = (const float*)d_in[2];
    const float* pb = (const float*)d_in[3];
    const float* se = (const float*)d_in[4];
    float* out = (float*)d_out;

    // 64 queries per block, bh fastest in blockIdx for L2 window locality
    const int nblocks = (BB * HH) * (NN / (NWARP * QT));  // 32 * 128 = 4096
    dsqg_kernel<<<nblocks, 256>>>(q, k, v, pb, se, out);
}